// round 7
// baseline (speedup 1.0000x reference)
#include <cuda_runtime.h>
#include <math.h>
#include <stdint.h>

// Problem constants
#define BATCH 8
#define P 4096
#define NPTS (BATCH * P)      // 32768
#define KNN 20
#define K21 21                // top-21 (self included, dropped at output)
#define LCOV 10
#define F 32
#define KS 5
#define NCLS 40
#define H1 256
#define RROWS 24
#define YSPLIT 4

// ---------------- scratch (no allocation allowed) ----------------
__device__ int    g_nbr[NPTS * KNN];
__device__ float  g_node[NPTS * F];
__device__ float  g_nrm[NPTS * 3];
__device__ double g_part[64 * 64];
__device__ float  g_mu[F];
__device__ float  g_gs[F];
__device__ float  g_ysp[YSPLIT * RROWS * F];

// --- 3 trivial kernels so knn_kernel lands on ncu's captured launch index ---
__global__ void pre0() {}
__global__ void pre1() {}
__global__ void pre2() {}

// ================= Kernel 1: KNN top-21, split-4, shfl bitonic merge =========
__device__ __forceinline__ void insert21(unsigned B[K21], unsigned key) {
#pragma unroll
    for (int v = K21 - 1; v >= 1; --v)
        B[v] = umin(B[v], umax(B[v - 1], key));
    B[0] = umin(B[0], key);
}

// Merge own ascending 21-list with partner's (lane ^ delta) via bitonic network.
// Pads to 32; result = lowest 21 of union, ascending. All register/fixed-index.
__device__ __forceinline__ void merge21(unsigned B[K21], int delta) {
    unsigned c[32];
#pragma unroll
    for (int i = 0; i < 32; ++i) {
        unsigned a = (i < K21) ? B[i] : 0xFFFFFFFFu;
        const int ri = 31 - i;
        unsigned b = (ri < K21) ? __shfl_xor_sync(0xFFFFFFFFu, B[ri], delta)
                                : 0xFFFFFFFFu;
        c[i] = umin(a, b);
    }
    // c is bitonic; sort ascending with 5-stage bitonic merger
#pragma unroll
    for (int d = 16; d >= 1; d >>= 1) {
#pragma unroll
        for (int i = 0; i < 32; ++i) {
            if ((i & d) == 0) {
                unsigned lo = umin(c[i], c[i | d]);
                unsigned hi = umax(c[i], c[i | d]);
                c[i] = lo; c[i | d] = hi;
            }
        }
    }
#pragma unroll
    for (int u = 0; u < K21; ++u) B[u] = c[u];
}

__global__ void __launch_bounds__(256, 3) knn_kernel(const float* __restrict__ pos) {
    extern __shared__ float4 sp[];                     // 4096 * 16 = 64KB

    const int batch = blockIdx.x >> 6;                 // 64 blocks per batch
    const int tid   = threadIdx.x;                     // 256
    const int qloc  = ((blockIdx.x & 63) << 6) + (tid >> 2);
    const int split = tid & 3;
    const float* bp = pos + (size_t)batch * P * 3;

    for (int i = tid; i < P; i += 256) {
        float x = bp[i * 3 + 0];
        float y = bp[i * 3 + 1];
        float z = bp[i * 3 + 2];
        sp[i] = make_float4(x, y, z, x * x + y * y + z * z);
    }
    __syncthreads();

    float4 q = sp[qloc];
    const float qx = -2.0f * q.x, qy = -2.0f * q.y, qz = -2.0f * q.z;
    const float q2 = q.w;

    unsigned B[K21];
#pragma unroll
    for (int u = 0; u < K21; ++u) B[u] = 0xFFFFFFFFu;

    unsigned q0 = 0xFFFFFFFFu, q1 = 0xFFFFFFFFu, q2b = 0xFFFFFFFFu, q3 = 0xFFFFFFFFu;
    int cnt = 0;

    const int lo = split << 10, hi = lo + (P >> 2);
#pragma unroll 2
    for (int j = lo; j < hi; ++j) {
        float4 p = sp[j];
        float d2 = fmaxf(fmaf(qx, p.x, fmaf(qy, p.y, fmaf(qz, p.z, p.w))) + q2, 0.0f);
        unsigned key = (__float_as_uint(d2) & 0xFFFFF000u) | (unsigned)j;
        if (key < B[K21 - 1]) {
            q0  = (cnt == 0) ? key : q0;
            q1  = (cnt == 1) ? key : q1;
            q2b = (cnt == 2) ? key : q2b;
            q3  = (cnt == 3) ? key : q3;
            ++cnt;
        }
        if (__any_sync(0xFFFFFFFFu, cnt == 4)) {
            insert21(B, q0);
            insert21(B, q1);
            insert21(B, q2b);
            insert21(B, q3);
            q0 = q1 = q2b = q3 = 0xFFFFFFFFu;
            cnt = 0;
        }
    }
    insert21(B, q0);
    insert21(B, q1);
    insert21(B, q2b);
    insert21(B, q3);

    // 4-way merge: lanes 4q..4q+3 hold disjoint sorted lists
    merge21(B, 1);   // (0,1) and (2,3)
    merge21(B, 2);   // (01, 23)

    // B[0] is self (d2~0 => smallest key); emit ranks 1..20
    if (split == 0) {
        const int gq = batch * P + qloc;
#pragma unroll
        for (int u = 1; u < K21; ++u)
            g_nbr[gq * KNN + (u - 1)] = batch * P + (int)(B[u] & 0xFFFu);
    }
}

// ================= Kernel 2: cov -> eig -> spline conv =================
__device__ __forceinline__ void pi3(const float M[6], float v[3], float* lam) {
    float v0 = 0.57735026918962576f, v1 = 0.57735026918962576f, v2 = 0.57735026918962576f;
#pragma unroll
    for (int it = 0; it < 5; ++it) {
        float a = fmaf(M[0], v0, fmaf(M[1], v1, M[2] * v2));
        float b = fmaf(M[1], v0, fmaf(M[3], v1, M[4] * v2));
        float c = fmaf(M[2], v0, fmaf(M[4], v1, M[5] * v2));
        float nrm = sqrtf(a * a + b * b + c * c);
        float inv = 1.0f / (nrm + 1e-12f);
        v0 = a * inv; v1 = b * inv; v2 = c * inv;
    }
    if (lam) {
        float a = fmaf(M[0], v0, fmaf(M[1], v1, M[2] * v2));
        float b = fmaf(M[1], v0, fmaf(M[3], v1, M[4] * v2));
        float c = fmaf(M[2], v0, fmaf(M[4], v1, M[5] * v2));
        *lam = a * v0 + b * v1 + c * v2;
    }
    v[0] = v0; v[1] = v1; v[2] = v2;
}

__global__ void feat_kernel(const float* __restrict__ pos,
                            const float* __restrict__ Wsp,
                            const float* __restrict__ root,
                            const float* __restrict__ bias) {
    __shared__ float sW[125 * 33];
    for (int i = threadIdx.x; i < 125 * F; i += blockDim.x) {
        int r = i >> 5, c = i & 31;
        sW[r * 33 + c] = Wsp[i];
    }
    __syncthreads();

    const int n = blockIdx.x * blockDim.x + threadIdx.x;
    const float px = pos[n * 3 + 0], py = pos[n * 3 + 1], pz = pos[n * 3 + 2];
    const int* nb = g_nbr + n * KNN;

    float c00 = 0, c01 = 0, c02 = 0, c11 = 0, c12 = 0, c22 = 0;
    for (int k = 0; k < LCOV; ++k) {
        int j = nb[k];
        float dx = pos[j * 3 + 0] - px;
        float dy = pos[j * 3 + 1] - py;
        float dz = pos[j * 3 + 2] - pz;
        c00 += dx * dx; c01 += dx * dy; c02 += dx * dz;
        c11 += dy * dy; c12 += dy * dz; c22 += dz * dz;
    }
    float M[6] = {c00, c01, c02, c11, c12, c22};
    float v1[3], v2[3];
    float lam1;
    pi3(M, v1, &lam1);
    float M2[6] = {
        c00 - lam1 * v1[0] * v1[0],
        c01 - lam1 * v1[0] * v1[1],
        c02 - lam1 * v1[0] * v1[2],
        c11 - lam1 * v1[1] * v1[1],
        c12 - lam1 * v1[1] * v1[2],
        c22 - lam1 * v1[2] * v1[2]};
    pi3(M2, v2, nullptr);
    float w0 = v1[1] * v2[2] - v1[2] * v2[1];
    float w1 = v1[2] * v2[0] - v1[0] * v2[2];
    float w2 = v1[0] * v2[1] - v1[1] * v2[0];
    float wn = sqrtf(w0 * w0 + w1 * w1 + w2 * w2);
    float winv = 1.0f / (wn + 1e-12f);
    w0 *= winv; w1 *= winv; w2 *= winv;

    float sz = 0.0f, ma = 0.0f;
    for (int k = 0; k < KNN; ++k) {
        int j = nb[k];
        float dx = pos[j * 3 + 0] - px;
        float dy = pos[j * 3 + 1] - py;
        float dz = pos[j * 3 + 2] - pz;
        float d0 = fmaf(dx, v1[0], fmaf(dy, v1[1], dz * v1[2]));
        float d1 = fmaf(dx, v2[0], fmaf(dy, v2[1], dz * v2[2]));
        float d2 = fmaf(dx, w0,    fmaf(dy, w1,    dz * w2));
        sz += d2;
        ma = fmaxf(ma, fmaxf(fabsf(d0), fmaxf(fabsf(d1), fabsf(d2))));
    }
    const float sgn = (sz > 0.0f) ? 1.0f : ((sz < 0.0f) ? -1.0f : 0.0f);

    float msg[F];
#pragma unroll
    for (int f = 0; f < F; ++f) msg[f] = 0.0f;

    for (int k = 0; k < KNN; ++k) {
        int j = nb[k];
        float dx = pos[j * 3 + 0] - px;
        float dy = pos[j * 3 + 1] - py;
        float dz = pos[j * 3 + 2] - pz;
        float d0 = fmaf(dx, v1[0], fmaf(dy, v1[1], dz * v1[2]));
        float d1 = fmaf(dx, v2[0], fmaf(dy, v2[1], dz * v2[2]));
        float d2 = fmaf(dx, w0,    fmaf(dy, w1,    dz * w2));
        d2 *= sgn;
        float u0 = d0 / ma * 0.5f + 0.5f;
        float u1 = d1 / ma * 0.5f + 0.5f;
        float u2 = d2 / ma * 0.5f + 0.5f;
        float t0 = u0 * (float)(KS - 1);
        float t1 = u1 * (float)(KS - 1);
        float t2 = u2 * (float)(KS - 1);
        float f0 = floorf(t0), f1 = floorf(t1), f2 = floorf(t2);
        float r0 = t0 - f0, r1 = t1 - f1, r2 = t2 - f2;
        int i0 = (int)f0, i1 = (int)f1, i2 = (int)f2;

#pragma unroll
        for (int s = 0; s < 8; ++s) {
            const int b0 = (s >> 2) & 1, b1 = (s >> 1) & 1, b2 = s & 1;
            int j0 = i0 + b0; j0 = j0 < 0 ? 0 : (j0 > KS - 1 ? KS - 1 : j0);
            int j1 = i1 + b1; j1 = j1 < 0 ? 0 : (j1 > KS - 1 ? KS - 1 : j1);
            int j2 = i2 + b2; j2 = j2 < 0 ? 0 : (j2 > KS - 1 ? KS - 1 : j2);
            float w = (b0 ? r0 : 1.0f - r0) * (b1 ? r1 : 1.0f - r1) * (b2 ? r2 : 1.0f - r2);
            const float* row = sW + ((j0 * KS + j1) * KS + j2) * 33;
#pragma unroll
            for (int f = 0; f < F; ++f) msg[f] = fmaf(w, row[f], msg[f]);
        }
    }

#pragma unroll
    for (int f = 0; f < F; ++f)
        g_node[n * F + f] = msg[f] / (float)KNN + root[f] + bias[f];
    g_nrm[n * 3 + 0] = w0;
    g_nrm[n * 3 + 1] = w1;
    g_nrm[n * 3 + 2] = w2;
}

// ================= Kernel 3: BatchNorm stats =================
__global__ void bn_partial() {
    const int f = threadIdx.x & 31, g = threadIdx.x >> 5;
    const int r0 = blockIdx.x * 512 + g;
    double s = 0.0, s2 = 0.0;
    for (int r = r0; r < blockIdx.x * 512 + 512; r += 8) {
        double x = (double)g_node[r * F + f];
        s += x; s2 += x * x;
    }
    __shared__ double sh[2][8][32];
    sh[0][g][f] = s; sh[1][g][f] = s2;
    __syncthreads();
    if (g == 0) {
        double a = 0.0, b = 0.0;
        for (int i = 0; i < 8; ++i) { a += sh[0][i][f]; b += sh[1][i][f]; }
        g_part[blockIdx.x * 64 + f]      = a;
        g_part[blockIdx.x * 64 + 32 + f] = b;
    }
}

__global__ void bn_final(const float* __restrict__ gamma) {
    __shared__ double sh[2][8][32];
    const int f = threadIdx.x & 31, g = threadIdx.x >> 5;   // 256 threads
    double s = 0.0, s2 = 0.0;
    for (int b = g; b < 64; b += 8) {
        s  += g_part[b * 64 + f];
        s2 += g_part[b * 64 + 32 + f];
    }
    sh[0][g][f] = s; sh[1][g][f] = s2;
    __syncthreads();
    if (g == 0) {
        double a = 0.0, b = 0.0;
        for (int i = 0; i < 8; ++i) { a += sh[0][i][f]; b += sh[1][i][f]; }
        double mu  = a / (double)NPTS;
        double var = b / (double)NPTS - mu * mu;
        float istd = 1.0f / sqrtf((float)var + 1e-5f);
        g_mu[f] = (float)mu;
        g_gs[f] = gamma[f] * istd;
    }
}

// ================= Kernel 4: sigmoid + regrouped partial means =================
__global__ void ys_kernel(const float* __restrict__ beta) {
    const int w = (blockIdx.x * blockDim.x + threadIdx.x) >> 5;
    const int lane = threadIdx.x & 31;
    if (w >= YSPLIT * RROWS * F) return;
    const int rf = w >> 2, part = w & (YSPLIT - 1);
    const int r = rf >> 5, f2 = rf & 31;
    const int base = r * (P * F) + f2;
    const int PSEG = P / YSPLIT;
    float acc = 0.0f;
    for (int p = part * PSEG + lane; p < (part + 1) * PSEG; p += 32) {
        int flat = base + p * F;
        int n = flat / 96;
        int rem = flat - n * 96;
        int f = rem / 3;
        int c = rem - f * 3;
        float x = (g_node[n * F + f] - g_mu[f]) * g_gs[f] + beta[f];
        float a = x * g_nrm[n * 3 + c];
        acc += 1.0f / (1.0f + __expf(-a));
    }
#pragma unroll
    for (int o = 16; o; o >>= 1) acc += __shfl_xor_sync(0xffffffffu, acc, o);
    if (lane == 0) g_ysp[w] = acc;
}

// ================= Kernel 5: MLP + log_softmax =================
__global__ void mlp_kernel(const float* __restrict__ W1, const float* __restrict__ b1,
                           const float* __restrict__ W2, const float* __restrict__ b2,
                           float* __restrict__ out) {
    __shared__ float sy[RROWS * F];
    __shared__ float sy1[RROWS * H1];
    __shared__ float slog[RROWS * NCLS];
    const int tid = threadIdx.x;   // 256
    for (int i = tid; i < RROWS * F; i += 256) {
        float a = 0.0f;
#pragma unroll
        for (int q = 0; q < YSPLIT; ++q) a += g_ysp[i * YSPLIT + q];
        sy[i] = a / (float)P;
    }
    __syncthreads();

    for (int i = tid; i < RROWS * H1; i += 256) {
        int r = i >> 8, j = i & 255;
        float a = b1[j];
#pragma unroll
        for (int f = 0; f < F; ++f) a = fmaf(sy[r * F + f], W1[f * H1 + j], a);
        sy1[i] = a > 0.0f ? a : expm1f(a);
    }
    __syncthreads();

    for (int i = tid; i < RROWS * NCLS; i += 256) {
        int r = i / NCLS, cls = i - r * NCLS;
        float a = b2[cls];
        for (int j = 0; j < H1; ++j) a = fmaf(sy1[r * H1 + j], W2[j * NCLS + cls], a);
        slog[i] = a;
    }
    __syncthreads();

    if (tid < RROWS) {
        float m = -3.4e38f;
        for (int c = 0; c < NCLS; ++c) m = fmaxf(m, slog[tid * NCLS + c]);
        float s = 0.0f;
        for (int c = 0; c < NCLS; ++c) s += expf(slog[tid * NCLS + c] - m);
        float l = logf(s);
        for (int c = 0; c < NCLS; ++c) out[tid * NCLS + c] = slog[tid * NCLS + c] - m - l;
    }
}

// ================= launch =================
extern "C" void kernel_launch(void* const* d_in, const int* in_sizes, int n_in,
                              void* d_out, int out_size) {
    const float* pos   = (const float*)d_in[0];
    const float* Wsp   = (const float*)d_in[1];
    const float* root  = (const float*)d_in[2];
    const float* bias  = (const float*)d_in[3];
    const float* gamma = (const float*)d_in[4];
    const float* beta  = (const float*)d_in[5];
    const float* W1    = (const float*)d_in[6];
    const float* b1    = (const float*)d_in[7];
    const float* W2    = (const float*)d_in[8];
    const float* b2    = (const float*)d_in[9];
    float* out = (float*)d_out;

    const int KNN_SMEM = P * 16;                       // 64KB tile only
    cudaFuncSetAttribute(knn_kernel, cudaFuncAttributeMaxDynamicSharedMemorySize, KNN_SMEM);

    // keep knn_kernel on ncu's captured launch index
    pre0<<<1, 32>>>();
    pre1<<<1, 32>>>();
    pre2<<<1, 32>>>();

    knn_kernel<<<512, 256, KNN_SMEM>>>(pos);
    feat_kernel<<<256, 128>>>(pos, Wsp, root, bias);
    bn_partial<<<64, 256>>>();
    bn_final<<<1, 256>>>(gamma);
    ys_kernel<<<(YSPLIT * RROWS * F * 32) / 256, 256>>>(beta);
    mlp_kernel<<<1, 256>>>(W1, b1, W2, b2, out);
}

// round 8
// speedup vs baseline: 1.8242x; 1.8242x over previous
#include <cuda_runtime.h>
#include <math.h>
#include <stdint.h>

// Problem constants
#define BATCH 8
#define P 4096
#define NPTS (BATCH * P)      // 32768
#define KNN 20
#define K21 21                // top-21 (self included, dropped at output)
#define LCOV 10
#define F 32
#define KS 5
#define NCLS 40
#define H1 256
#define RROWS 24
#define YSPLIT 4

// ---------------- scratch (no allocation allowed) ----------------
__device__ int    g_nbr[NPTS * KNN];
__device__ float  g_node[NPTS * F];
__device__ float  g_nrm[NPTS * 3];
__device__ double g_part[64 * 64];
__device__ float  g_mu[F];
__device__ float  g_gs[F];
__device__ float  g_ysp[YSPLIT * RROWS * F];

// --- 3 trivial kernels so knn_kernel lands on ncu's captured launch index ---
__global__ void pre0() {}
__global__ void pre1() {}
__global__ void pre2() {}

// ================= Kernel 1: KNN top-21, split-4 (bank-staggered) ============
__device__ __forceinline__ void insert21(unsigned B[K21], unsigned key) {
#pragma unroll
    for (int v = K21 - 1; v >= 1; --v)
        B[v] = umin(B[v], umax(B[v - 1], key));
    B[0] = umin(B[0], key);
}

// Merge own ascending 21-list with partner's (lane ^ delta) via bitonic network.
__device__ __forceinline__ void merge21(unsigned B[K21], int delta) {
    unsigned c[32];
#pragma unroll
    for (int i = 0; i < 32; ++i) {
        unsigned a = (i < K21) ? B[i] : 0xFFFFFFFFu;
        const int ri = 31 - i;
        unsigned b = (ri < K21) ? __shfl_xor_sync(0xFFFFFFFFu, B[ri], delta)
                                : 0xFFFFFFFFu;
        c[i] = umin(a, b);
    }
#pragma unroll
    for (int d = 16; d >= 1; d >>= 1) {
#pragma unroll
        for (int i = 0; i < 32; ++i) {
            if ((i & d) == 0) {
                unsigned lo = umin(c[i], c[i | d]);
                unsigned hi = umax(c[i], c[i | d]);
                c[i] = lo; c[i | d] = hi;
            }
        }
    }
#pragma unroll
    for (int u = 0; u < K21; ++u) B[u] = c[u];
}

__global__ void __launch_bounds__(256, 3) knn_kernel(const float* __restrict__ pos) {
    extern __shared__ float4 sp[];                     // 4096 * 16 = 64KB

    const int batch = blockIdx.x >> 6;                 // 64 blocks per batch
    const int tid   = threadIdx.x;                     // 256
    const int qloc  = ((blockIdx.x & 63) << 6) + (tid >> 2);
    const int split = tid & 3;
    const float* bp = pos + (size_t)batch * P * 3;

    for (int i = tid; i < P; i += 256) {
        float x = bp[i * 3 + 0];
        float y = bp[i * 3 + 1];
        float z = bp[i * 3 + 2];
        sp[i] = make_float4(x, y, z, x * x + y * y + z * z);
    }
    __syncthreads();

    float4 q = sp[qloc];
    const float qx = -2.0f * q.x, qy = -2.0f * q.y, qz = -2.0f * q.z;
    const float q2 = q.w;

    unsigned B[K21];
#pragma unroll
    for (int u = 0; u < K21; ++u) B[u] = 0xFFFFFFFFu;

    unsigned q0 = 0xFFFFFFFFu, q1 = 0xFFFFFFFFu, q2b = 0xFFFFFFFFu, q3 = 0xFFFFFFFFu;
    int cnt = 0;

    // split s scans [s*1024, (s+1)*1024), rotated by 2*s so concurrent lane
    // indices differ mod 8 -> conflict-free 16-byte shared loads
    const int lo  = split << 10;
    const int rot = split << 1;
#pragma unroll 2
    for (int i = 0; i < (P >> 2); ++i) {
        const int j = lo + ((i + rot) & ((P >> 2) - 1));
        float4 p = sp[j];
        float d2 = fmaxf(fmaf(qx, p.x, fmaf(qy, p.y, fmaf(qz, p.z, p.w))) + q2, 0.0f);
        unsigned key = (__float_as_uint(d2) & 0xFFFFF000u) | (unsigned)j;
        if (key < B[K21 - 1]) {
            q0  = (cnt == 0) ? key : q0;
            q1  = (cnt == 1) ? key : q1;
            q2b = (cnt == 2) ? key : q2b;
            q3  = (cnt == 3) ? key : q3;
            ++cnt;
        }
        if (__any_sync(0xFFFFFFFFu, cnt == 4)) {
            insert21(B, q0);
            insert21(B, q1);
            insert21(B, q2b);
            insert21(B, q3);
            q0 = q1 = q2b = q3 = 0xFFFFFFFFu;
            cnt = 0;
        }
    }
    insert21(B, q0);
    insert21(B, q1);
    insert21(B, q2b);
    insert21(B, q3);

    // 4-way merge: lanes 4q..4q+3 hold disjoint sorted lists
    merge21(B, 1);   // (0,1) and (2,3)
    merge21(B, 2);   // (01, 23)

    // B[0] is self (d2~0 => smallest key); emit ranks 1..20
    if (split == 0) {
        const int gq = batch * P + qloc;
#pragma unroll
        for (int u = 1; u < K21; ++u)
            g_nbr[gq * KNN + (u - 1)] = batch * P + (int)(B[u] & 0xFFFu);
    }
}

// ================= Kernel 2: cov -> eig -> spline conv =================
__device__ __forceinline__ void pi3(const float M[6], float v[3], float* lam) {
    float v0 = 0.57735026918962576f, v1 = 0.57735026918962576f, v2 = 0.57735026918962576f;
#pragma unroll
    for (int it = 0; it < 5; ++it) {
        float a = fmaf(M[0], v0, fmaf(M[1], v1, M[2] * v2));
        float b = fmaf(M[1], v0, fmaf(M[3], v1, M[4] * v2));
        float c = fmaf(M[2], v0, fmaf(M[4], v1, M[5] * v2));
        float nrm = sqrtf(a * a + b * b + c * c);
        float inv = 1.0f / (nrm + 1e-12f);
        v0 = a * inv; v1 = b * inv; v2 = c * inv;
    }
    if (lam) {
        float a = fmaf(M[0], v0, fmaf(M[1], v1, M[2] * v2));
        float b = fmaf(M[1], v0, fmaf(M[3], v1, M[4] * v2));
        float c = fmaf(M[2], v0, fmaf(M[4], v1, M[5] * v2));
        *lam = a * v0 + b * v1 + c * v2;
    }
    v[0] = v0; v[1] = v1; v[2] = v2;
}

__global__ void feat_kernel(const float* __restrict__ pos,
                            const float* __restrict__ Wsp,
                            const float* __restrict__ root,
                            const float* __restrict__ bias) {
    __shared__ float sW[125 * 33];
    for (int i = threadIdx.x; i < 125 * F; i += blockDim.x) {
        int r = i >> 5, c = i & 31;
        sW[r * 33 + c] = Wsp[i];
    }
    __syncthreads();

    const int n = blockIdx.x * blockDim.x + threadIdx.x;
    const float px = pos[n * 3 + 0], py = pos[n * 3 + 1], pz = pos[n * 3 + 2];
    const int* nb = g_nbr + n * KNN;

    float c00 = 0, c01 = 0, c02 = 0, c11 = 0, c12 = 0, c22 = 0;
    for (int k = 0; k < LCOV; ++k) {
        int j = nb[k];
        float dx = pos[j * 3 + 0] - px;
        float dy = pos[j * 3 + 1] - py;
        float dz = pos[j * 3 + 2] - pz;
        c00 += dx * dx; c01 += dx * dy; c02 += dx * dz;
        c11 += dy * dy; c12 += dy * dz; c22 += dz * dz;
    }
    float M[6] = {c00, c01, c02, c11, c12, c22};
    float v1[3], v2[3];
    float lam1;
    pi3(M, v1, &lam1);
    float M2[6] = {
        c00 - lam1 * v1[0] * v1[0],
        c01 - lam1 * v1[0] * v1[1],
        c02 - lam1 * v1[0] * v1[2],
        c11 - lam1 * v1[1] * v1[1],
        c12 - lam1 * v1[1] * v1[2],
        c22 - lam1 * v1[2] * v1[2]};
    pi3(M2, v2, nullptr);
    float w0 = v1[1] * v2[2] - v1[2] * v2[1];
    float w1 = v1[2] * v2[0] - v1[0] * v2[2];
    float w2 = v1[0] * v2[1] - v1[1] * v2[0];
    float wn = sqrtf(w0 * w0 + w1 * w1 + w2 * w2);
    float winv = 1.0f / (wn + 1e-12f);
    w0 *= winv; w1 *= winv; w2 *= winv;

    float sz = 0.0f, ma = 0.0f;
    for (int k = 0; k < KNN; ++k) {
        int j = nb[k];
        float dx = pos[j * 3 + 0] - px;
        float dy = pos[j * 3 + 1] - py;
        float dz = pos[j * 3 + 2] - pz;
        float d0 = fmaf(dx, v1[0], fmaf(dy, v1[1], dz * v1[2]));
        float d1 = fmaf(dx, v2[0], fmaf(dy, v2[1], dz * v2[2]));
        float d2 = fmaf(dx, w0,    fmaf(dy, w1,    dz * w2));
        sz += d2;
        ma = fmaxf(ma, fmaxf(fabsf(d0), fmaxf(fabsf(d1), fabsf(d2))));
    }
    const float sgn = (sz > 0.0f) ? 1.0f : ((sz < 0.0f) ? -1.0f : 0.0f);

    float msg[F];
#pragma unroll
    for (int f = 0; f < F; ++f) msg[f] = 0.0f;

    for (int k = 0; k < KNN; ++k) {
        int j = nb[k];
        float dx = pos[j * 3 + 0] - px;
        float dy = pos[j * 3 + 1] - py;
        float dz = pos[j * 3 + 2] - pz;
        float d0 = fmaf(dx, v1[0], fmaf(dy, v1[1], dz * v1[2]));
        float d1 = fmaf(dx, v2[0], fmaf(dy, v2[1], dz * v2[2]));
        float d2 = fmaf(dx, w0,    fmaf(dy, w1,    dz * w2));
        d2 *= sgn;
        float u0 = d0 / ma * 0.5f + 0.5f;
        float u1 = d1 / ma * 0.5f + 0.5f;
        float u2 = d2 / ma * 0.5f + 0.5f;
        float t0 = u0 * (float)(KS - 1);
        float t1 = u1 * (float)(KS - 1);
        float t2 = u2 * (float)(KS - 1);
        float f0 = floorf(t0), f1 = floorf(t1), f2 = floorf(t2);
        float r0 = t0 - f0, r1 = t1 - f1, r2 = t2 - f2;
        int i0 = (int)f0, i1 = (int)f1, i2 = (int)f2;

#pragma unroll
        for (int s = 0; s < 8; ++s) {
            const int b0 = (s >> 2) & 1, b1 = (s >> 1) & 1, b2 = s & 1;
            int j0 = i0 + b0; j0 = j0 < 0 ? 0 : (j0 > KS - 1 ? KS - 1 : j0);
            int j1 = i1 + b1; j1 = j1 < 0 ? 0 : (j1 > KS - 1 ? KS - 1 : j1);
            int j2 = i2 + b2; j2 = j2 < 0 ? 0 : (j2 > KS - 1 ? KS - 1 : j2);
            float w = (b0 ? r0 : 1.0f - r0) * (b1 ? r1 : 1.0f - r1) * (b2 ? r2 : 1.0f - r2);
            const float* row = sW + ((j0 * KS + j1) * KS + j2) * 33;
#pragma unroll
            for (int f = 0; f < F; ++f) msg[f] = fmaf(w, row[f], msg[f]);
        }
    }

#pragma unroll
    for (int f = 0; f < F; ++f)
        g_node[n * F + f] = msg[f] / (float)KNN + root[f] + bias[f];
    g_nrm[n * 3 + 0] = w0;
    g_nrm[n * 3 + 1] = w1;
    g_nrm[n * 3 + 2] = w2;
}

// ================= Kernel 3: BatchNorm stats =================
__global__ void bn_partial() {
    const int f = threadIdx.x & 31, g = threadIdx.x >> 5;
    const int r0 = blockIdx.x * 512 + g;
    double s = 0.0, s2 = 0.0;
    for (int r = r0; r < blockIdx.x * 512 + 512; r += 8) {
        double x = (double)g_node[r * F + f];
        s += x; s2 += x * x;
    }
    __shared__ double sh[2][8][32];
    sh[0][g][f] = s; sh[1][g][f] = s2;
    __syncthreads();
    if (g == 0) {
        double a = 0.0, b = 0.0;
        for (int i = 0; i < 8; ++i) { a += sh[0][i][f]; b += sh[1][i][f]; }
        g_part[blockIdx.x * 64 + f]      = a;
        g_part[blockIdx.x * 64 + 32 + f] = b;
    }
}

__global__ void bn_final(const float* __restrict__ gamma) {
    __shared__ double sh[2][8][32];
    const int f = threadIdx.x & 31, g = threadIdx.x >> 5;   // 256 threads
    double s = 0.0, s2 = 0.0;
    for (int b = g; b < 64; b += 8) {
        s  += g_part[b * 64 + f];
        s2 += g_part[b * 64 + 32 + f];
    }
    sh[0][g][f] = s; sh[1][g][f] = s2;
    __syncthreads();
    if (g == 0) {
        double a = 0.0, b = 0.0;
        for (int i = 0; i < 8; ++i) { a += sh[0][i][f]; b += sh[1][i][f]; }
        double mu  = a / (double)NPTS;
        double var = b / (double)NPTS - mu * mu;
        float istd = 1.0f / sqrtf((float)var + 1e-5f);
        g_mu[f] = (float)mu;
        g_gs[f] = gamma[f] * istd;
    }
}

// ================= Kernel 4: sigmoid + regrouped partial means =================
__global__ void ys_kernel(const float* __restrict__ beta) {
    const int w = (blockIdx.x * blockDim.x + threadIdx.x) >> 5;
    const int lane = threadIdx.x & 31;
    if (w >= YSPLIT * RROWS * F) return;
    const int rf = w >> 2, part = w & (YSPLIT - 1);
    const int r = rf >> 5, f2 = rf & 31;
    const int base = r * (P * F) + f2;
    const int PSEG = P / YSPLIT;
    float acc = 0.0f;
    for (int p = part * PSEG + lane; p < (part + 1) * PSEG; p += 32) {
        int flat = base + p * F;
        int n = flat / 96;
        int rem = flat - n * 96;
        int f = rem / 3;
        int c = rem - f * 3;
        float x = (g_node[n * F + f] - g_mu[f]) * g_gs[f] + beta[f];
        float a = x * g_nrm[n * 3 + c];
        acc += 1.0f / (1.0f + __expf(-a));
    }
#pragma unroll
    for (int o = 16; o; o >>= 1) acc += __shfl_xor_sync(0xffffffffu, acc, o);
    if (lane == 0) g_ysp[w] = acc;
}

// ================= Kernel 5: MLP + log_softmax =================
__global__ void mlp_kernel(const float* __restrict__ W1, const float* __restrict__ b1,
                           const float* __restrict__ W2, const float* __restrict__ b2,
                           float* __restrict__ out) {
    __shared__ float sy[RROWS * F];
    __shared__ float sy1[RROWS * H1];
    __shared__ float slog[RROWS * NCLS];
    const int tid = threadIdx.x;   // 256
    for (int i = tid; i < RROWS * F; i += 256) {
        float a = 0.0f;
#pragma unroll
        for (int q = 0; q < YSPLIT; ++q) a += g_ysp[i * YSPLIT + q];
        sy[i] = a / (float)P;
    }
    __syncthreads();

    for (int i = tid; i < RROWS * H1; i += 256) {
        int r = i >> 8, j = i & 255;
        float a = b1[j];
#pragma unroll
        for (int f = 0; f < F; ++f) a = fmaf(sy[r * F + f], W1[f * H1 + j], a);
        sy1[i] = a > 0.0f ? a : expm1f(a);
    }
    __syncthreads();

    for (int i = tid; i < RROWS * NCLS; i += 256) {
        int r = i / NCLS, cls = i - r * NCLS;
        float a = b2[cls];
        for (int j = 0; j < H1; ++j) a = fmaf(sy1[r * H1 + j], W2[j * NCLS + cls], a);
        slog[i] = a;
    }
    __syncthreads();

    if (tid < RROWS) {
        float m = -3.4e38f;
        for (int c = 0; c < NCLS; ++c) m = fmaxf(m, slog[tid * NCLS + c]);
        float s = 0.0f;
        for (int c = 0; c < NCLS; ++c) s += expf(slog[tid * NCLS + c] - m);
        float l = logf(s);
        for (int c = 0; c < NCLS; ++c) out[tid * NCLS + c] = slog[tid * NCLS + c] - m - l;
    }
}

// ================= launch =================
extern "C" void kernel_launch(void* const* d_in, const int* in_sizes, int n_in,
                              void* d_out, int out_size) {
    const float* pos   = (const float*)d_in[0];
    const float* Wsp   = (const float*)d_in[1];
    const float* root  = (const float*)d_in[2];
    const float* bias  = (const float*)d_in[3];
    const float* gamma = (const float*)d_in[4];
    const float* beta  = (const float*)d_in[5];
    const float* W1    = (const float*)d_in[6];
    const float* b1    = (const float*)d_in[7];
    const float* W2    = (const float*)d_in[8];
    const float* b2    = (const float*)d_in[9];
    float* out = (float*)d_out;

    const int KNN_SMEM = P * 16;                       // 64KB tile only
    cudaFuncSetAttribute(knn_kernel, cudaFuncAttributeMaxDynamicSharedMemorySize, KNN_SMEM);

    // keep knn_kernel on ncu's captured launch index
    pre0<<<1, 32>>>();
    pre1<<<1, 32>>>();
    pre2<<<1, 32>>>();

    knn_kernel<<<512, 256, KNN_SMEM>>>(pos);
    feat_kernel<<<256, 128>>>(pos, Wsp, root, bias);
    bn_partial<<<64, 256>>>();
    bn_final<<<1, 256>>>(gamma);
    ys_kernel<<<(YSPLIT * RROWS * F * 32) / 256, 256>>>(beta);
    mlp_kernel<<<1, 256>>>(W1, b1, W2, b2, out);
}

// round 11
// speedup vs baseline: 1.8623x; 1.0209x over previous
#include <cuda_runtime.h>
#include <math.h>
#include <stdint.h>

// Problem constants
#define BATCH 8
#define P 4096
#define NPTS (BATCH * P)      // 32768
#define KNN 20
#define K21 21                // top-21 (self included, dropped at output)
#define LCOV 10
#define F 32
#define KS 5
#define NCLS 40
#define H1 256
#define RROWS 24
#define YSPLIT 4

// ---------------- scratch (no allocation allowed) ----------------
__device__ int    g_nbr[NPTS * KNN];
__device__ float  g_node[NPTS * F];
__device__ float  g_nrm[NPTS * 3];
__device__ double g_part[64 * 64];
__device__ float  g_mu[F];
__device__ float  g_gs[F];
__device__ float  g_ysp[YSPLIT * RROWS * F];

// --- 3 trivial kernels so knn_kernel lands on ncu's captured launch index ---
__global__ void pre0() {}
__global__ void pre1() {}
__global__ void pre2() {}

// ================= Kernel 1: KNN top-21, split-4, shared thresholds ==========
__device__ __forceinline__ void insert21(unsigned B[K21], unsigned key) {
#pragma unroll
    for (int v = K21 - 1; v >= 1; --v)
        B[v] = umin(B[v], umax(B[v - 1], key));
    B[0] = umin(B[0], key);
}

// Merge own ascending 21-list with partner's (lane ^ delta) via bitonic network.
__device__ __forceinline__ void merge21(unsigned B[K21], int delta) {
    unsigned c[32];
#pragma unroll
    for (int i = 0; i < 32; ++i) {
        unsigned a = (i < K21) ? B[i] : 0xFFFFFFFFu;
        const int ri = 31 - i;
        unsigned b = (ri < K21) ? __shfl_xor_sync(0xFFFFFFFFu, B[ri], delta)
                                : 0xFFFFFFFFu;
        c[i] = umin(a, b);
    }
#pragma unroll
    for (int d = 16; d >= 1; d >>= 1) {
#pragma unroll
        for (int i = 0; i < 32; ++i) {
            if ((i & d) == 0) {
                unsigned lo = umin(c[i], c[i | d]);
                unsigned hi = umax(c[i], c[i | d]);
                c[i] = lo; c[i | d] = hi;
            }
        }
    }
#pragma unroll
    for (int u = 0; u < K21; ++u) B[u] = c[u];
}

__global__ void __launch_bounds__(256, 3) knn_kernel(const float* __restrict__ pos) {
    extern __shared__ float4 sp[];                     // 4096 * 16 = 64KB

    const int batch = blockIdx.x >> 6;                 // 64 blocks per batch
    const int tid   = threadIdx.x;                     // 256
    const int qloc  = ((blockIdx.x & 63) << 6) + (tid >> 2);
    const int split = tid & 3;
    const float* bp = pos + (size_t)batch * P * 3;

    for (int i = tid; i < P; i += 256) {
        float x = bp[i * 3 + 0];
        float y = bp[i * 3 + 1];
        float z = bp[i * 3 + 2];
        sp[i] = make_float4(x, y, z, x * x + y * y + z * z);
    }
    __syncthreads();

    float4 q = sp[qloc];
    const float qx = -2.0f * q.x, qy = -2.0f * q.y, qz = -2.0f * q.z;
    const float q2 = q.w;

    unsigned B[K21];
#pragma unroll
    for (int u = 0; u < K21; ++u) B[u] = 0xFFFFFFFFu;

    unsigned q0 = 0xFFFFFFFFu, q1 = 0xFFFFFFFFu, q2b = 0xFFFFFFFFu, q3 = 0xFFFFFFFFu;
    int cnt = 0;
    unsigned thr = 0xFFFFFFFFu;                        // shared admission threshold

    // split s scans [s*1024, (s+1)*1024), rotated by 2*s so concurrent lane
    // indices differ mod 8 -> conflict-free 16-byte shared loads.
    // 16 chunks of 64; after each chunk, tighten thr across the 4 split lanes
    // of the same query (exact: see proof in commit message).
    const int lo  = split << 10;
    const int rot = split << 1;
    int i = 0;
    for (int c = 0; c < 16; ++c) {
#pragma unroll 2
        for (int ii = 0; ii < 64; ++ii, ++i) {
            const int j = lo + ((i + rot) & ((P >> 2) - 1));
            float4 p = sp[j];
            float d2 = fmaxf(fmaf(qx, p.x, fmaf(qy, p.y, fmaf(qz, p.z, p.w))) + q2, 0.0f);
            unsigned key = (__float_as_uint(d2) & 0xFFFFF000u) | (unsigned)j;
            if (key < thr) {
                q0  = (cnt == 0) ? key : q0;
                q1  = (cnt == 1) ? key : q1;
                q2b = (cnt == 2) ? key : q2b;
                q3  = (cnt == 3) ? key : q3;
                ++cnt;
            }
            if (__any_sync(0xFFFFFFFFu, cnt == 4)) {
                insert21(B, q0);
                insert21(B, q1);
                insert21(B, q2b);
                insert21(B, q3);
                q0 = q1 = q2b = q3 = 0xFFFFFFFFu;
                cnt = 0;
                thr = umin(thr, B[K21 - 1]);
            }
        }
        unsigned t = B[K21 - 1];
        t = umin(t, __shfl_xor_sync(0xFFFFFFFFu, t, 1));
        t = umin(t, __shfl_xor_sync(0xFFFFFFFFu, t, 2));
        thr = umin(thr, t);
    }
    insert21(B, q0);
    insert21(B, q1);
    insert21(B, q2b);
    insert21(B, q3);

    // 4-way merge: lanes 4q..4q+3 hold disjoint sorted lists
    merge21(B, 1);   // (0,1) and (2,3)
    merge21(B, 2);   // (01, 23)

    // B[0] is self (d2~0 => smallest key); emit ranks 1..20
    if (split == 0) {
        const int gq = batch * P + qloc;
#pragma unroll
        for (int u = 1; u < K21; ++u)
            g_nbr[gq * KNN + (u - 1)] = batch * P + (int)(B[u] & 0xFFFu);
    }
}

// ================= Kernel 2: cov -> eig -> spline conv =================
__device__ __forceinline__ void pi3(const float M[6], float v[3], float* lam) {
    float v0 = 0.57735026918962576f, v1 = 0.57735026918962576f, v2 = 0.57735026918962576f;
#pragma unroll
    for (int it = 0; it < 5; ++it) {
        float a = fmaf(M[0], v0, fmaf(M[1], v1, M[2] * v2));
        float b = fmaf(M[1], v0, fmaf(M[3], v1, M[4] * v2));
        float c = fmaf(M[2], v0, fmaf(M[4], v1, M[5] * v2));
        float nrm = sqrtf(a * a + b * b + c * c);
        float inv = 1.0f / (nrm + 1e-12f);
        v0 = a * inv; v1 = b * inv; v2 = c * inv;
    }
    if (lam) {
        float a = fmaf(M[0], v0, fmaf(M[1], v1, M[2] * v2));
        float b = fmaf(M[1], v0, fmaf(M[3], v1, M[4] * v2));
        float c = fmaf(M[2], v0, fmaf(M[4], v1, M[5] * v2));
        *lam = a * v0 + b * v1 + c * v2;
    }
    v[0] = v0; v[1] = v1; v[2] = v2;
}

__global__ void feat_kernel(const float* __restrict__ pos,
                            const float* __restrict__ Wsp,
                            const float* __restrict__ root,
                            const float* __restrict__ bias) {
    __shared__ float sW[125 * 33];
    for (int i = threadIdx.x; i < 125 * F; i += blockDim.x) {
        int r = i >> 5, c = i & 31;
        sW[r * 33 + c] = Wsp[i];
    }
    __syncthreads();

    const int n = blockIdx.x * blockDim.x + threadIdx.x;
    const float px = pos[n * 3 + 0], py = pos[n * 3 + 1], pz = pos[n * 3 + 2];
    const int* nb = g_nbr + n * KNN;

    float c00 = 0, c01 = 0, c02 = 0, c11 = 0, c12 = 0, c22 = 0;
    for (int k = 0; k < LCOV; ++k) {
        int j = nb[k];
        float dx = pos[j * 3 + 0] - px;
        float dy = pos[j * 3 + 1] - py;
        float dz = pos[j * 3 + 2] - pz;
        c00 += dx * dx; c01 += dx * dy; c02 += dx * dz;
        c11 += dy * dy; c12 += dy * dz; c22 += dz * dz;
    }
    float M[6] = {c00, c01, c02, c11, c12, c22};
    float v1[3], v2[3];
    float lam1;
    pi3(M, v1, &lam1);
    float M2[6] = {
        c00 - lam1 * v1[0] * v1[0],
        c01 - lam1 * v1[0] * v1[1],
        c02 - lam1 * v1[0] * v1[2],
        c11 - lam1 * v1[1] * v1[1],
        c12 - lam1 * v1[1] * v1[2],
        c22 - lam1 * v1[2] * v1[2]};
    pi3(M2, v2, nullptr);
    float w0 = v1[1] * v2[2] - v1[2] * v2[1];
    float w1 = v1[2] * v2[0] - v1[0] * v2[2];
    float w2 = v1[0] * v2[1] - v1[1] * v2[0];
    float wn = sqrtf(w0 * w0 + w1 * w1 + w2 * w2);
    float winv = 1.0f / (wn + 1e-12f);
    w0 *= winv; w1 *= winv; w2 *= winv;

    float sz = 0.0f, ma = 0.0f;
    for (int k = 0; k < KNN; ++k) {
        int j = nb[k];
        float dx = pos[j * 3 + 0] - px;
        float dy = pos[j * 3 + 1] - py;
        float dz = pos[j * 3 + 2] - pz;
        float d0 = fmaf(dx, v1[0], fmaf(dy, v1[1], dz * v1[2]));
        float d1 = fmaf(dx, v2[0], fmaf(dy, v2[1], dz * v2[2]));
        float d2 = fmaf(dx, w0,    fmaf(dy, w1,    dz * w2));
        sz += d2;
        ma = fmaxf(ma, fmaxf(fabsf(d0), fmaxf(fabsf(d1), fabsf(d2))));
    }
    const float sgn = (sz > 0.0f) ? 1.0f : ((sz < 0.0f) ? -1.0f : 0.0f);

    float msg[F];
#pragma unroll
    for (int f = 0; f < F; ++f) msg[f] = 0.0f;

    for (int k = 0; k < KNN; ++k) {
        int j = nb[k];
        float dx = pos[j * 3 + 0] - px;
        float dy = pos[j * 3 + 1] - py;
        float dz = pos[j * 3 + 2] - pz;
        float d0 = fmaf(dx, v1[0], fmaf(dy, v1[1], dz * v1[2]));
        float d1 = fmaf(dx, v2[0], fmaf(dy, v2[1], dz * v2[2]));
        float d2 = fmaf(dx, w0,    fmaf(dy, w1,    dz * w2));
        d2 *= sgn;
        float u0 = d0 / ma * 0.5f + 0.5f;
        float u1 = d1 / ma * 0.5f + 0.5f;
        float u2 = d2 / ma * 0.5f + 0.5f;
        float t0 = u0 * (float)(KS - 1);
        float t1 = u1 * (float)(KS - 1);
        float t2 = u2 * (float)(KS - 1);
        float f0 = floorf(t0), f1 = floorf(t1), f2 = floorf(t2);
        float r0 = t0 - f0, r1 = t1 - f1, r2 = t2 - f2;
        int i0 = (int)f0, i1 = (int)f1, i2 = (int)f2;

#pragma unroll
        for (int s = 0; s < 8; ++s) {
            const int b0 = (s >> 2) & 1, b1 = (s >> 1) & 1, b2 = s & 1;
            int j0 = i0 + b0; j0 = j0 < 0 ? 0 : (j0 > KS - 1 ? KS - 1 : j0);
            int j1 = i1 + b1; j1 = j1 < 0 ? 0 : (j1 > KS - 1 ? KS - 1 : j1);
            int j2 = i2 + b2; j2 = j2 < 0 ? 0 : (j2 > KS - 1 ? KS - 1 : j2);
            float w = (b0 ? r0 : 1.0f - r0) * (b1 ? r1 : 1.0f - r1) * (b2 ? r2 : 1.0f - r2);
            const float* row = sW + ((j0 * KS + j1) * KS + j2) * 33;
#pragma unroll
            for (int f = 0; f < F; ++f) msg[f] = fmaf(w, row[f], msg[f]);
        }
    }

#pragma unroll
    for (int f = 0; f < F; ++f)
        g_node[n * F + f] = msg[f] / (float)KNN + root[f] + bias[f];
    g_nrm[n * 3 + 0] = w0;
    g_nrm[n * 3 + 1] = w1;
    g_nrm[n * 3 + 2] = w2;
}

// ================= Kernel 3: BatchNorm stats =================
__global__ void bn_partial() {
    const int f = threadIdx.x & 31, g = threadIdx.x >> 5;
    const int r0 = blockIdx.x * 512 + g;
    double s = 0.0, s2 = 0.0;
    for (int r = r0; r < blockIdx.x * 512 + 512; r += 8) {
        double x = (double)g_node[r * F + f];
        s += x; s2 += x * x;
    }
    __shared__ double sh[2][8][32];
    sh[0][g][f] = s; sh[1][g][f] = s2;
    __syncthreads();
    if (g == 0) {
        double a = 0.0, b = 0.0;
        for (int i = 0; i < 8; ++i) { a += sh[0][i][f]; b += sh[1][i][f]; }
        g_part[blockIdx.x * 64 + f]      = a;
        g_part[blockIdx.x * 64 + 32 + f] = b;
    }
}

__global__ void bn_final(const float* __restrict__ gamma) {
    __shared__ double sh[2][8][32];
    const int f = threadIdx.x & 31, g = threadIdx.x >> 5;   // 256 threads
    double s = 0.0, s2 = 0.0;
    for (int b = g; b < 64; b += 8) {
        s  += g_part[b * 64 + f];
        s2 += g_part[b * 64 + 32 + f];
    }
    sh[0][g][f] = s; sh[1][g][f] = s2;
    __syncthreads();
    if (g == 0) {
        double a = 0.0, b = 0.0;
        for (int i = 0; i < 8; ++i) { a += sh[0][i][f]; b += sh[1][i][f]; }
        double mu  = a / (double)NPTS;
        double var = b / (double)NPTS - mu * mu;
        float istd = 1.0f / sqrtf((float)var + 1e-5f);
        g_mu[f] = (float)mu;
        g_gs[f] = gamma[f] * istd;
    }
}

// ================= Kernel 4: sigmoid + regrouped partial means =================
__global__ void ys_kernel(const float* __restrict__ beta) {
    const int w = (blockIdx.x * blockDim.x + threadIdx.x) >> 5;
    const int lane = threadIdx.x & 31;
    if (w >= YSPLIT * RROWS * F) return;
    const int rf = w >> 2, part = w & (YSPLIT - 1);
    const int r = rf >> 5, f2 = rf & 31;
    const int base = r * (P * F) + f2;
    const int PSEG = P / YSPLIT;
    float acc = 0.0f;
    for (int p = part * PSEG + lane; p < (part + 1) * PSEG; p += 32) {
        int flat = base + p * F;
        int n = flat / 96;
        int rem = flat - n * 96;
        int f = rem / 3;
        int c = rem - f * 3;
        float x = (g_node[n * F + f] - g_mu[f]) * g_gs[f] + beta[f];
        float a = x * g_nrm[n * 3 + c];
        acc += 1.0f / (1.0f + __expf(-a));
    }
#pragma unroll
    for (int o = 16; o; o >>= 1) acc += __shfl_xor_sync(0xffffffffu, acc, o);
    if (lane == 0) g_ysp[w] = acc;
}

// ================= Kernel 5: MLP + log_softmax =================
__global__ void mlp_kernel(const float* __restrict__ W1, const float* __restrict__ b1,
                           const float* __restrict__ W2, const float* __restrict__ b2,
                           float* __restrict__ out) {
    __shared__ float sy[RROWS * F];
    __shared__ float sy1[RROWS * H1];
    __shared__ float slog[RROWS * NCLS];
    const int tid = threadIdx.x;   // 256
    for (int i = tid; i < RROWS * F; i += 256) {
        float a = 0.0f;
#pragma unroll
        for (int q = 0; q < YSPLIT; ++q) a += g_ysp[i * YSPLIT + q];
        sy[i] = a / (float)P;
    }
    __syncthreads();

    for (int i = tid; i < RROWS * H1; i += 256) {
        int r = i >> 8, j = i & 255;
        float a = b1[j];
#pragma unroll
        for (int f = 0; f < F; ++f) a = fmaf(sy[r * F + f], W1[f * H1 + j], a);
        sy1[i] = a > 0.0f ? a : expm1f(a);
    }
    __syncthreads();

    for (int i = tid; i < RROWS * NCLS; i += 256) {
        int r = i / NCLS, cls = i - r * NCLS;
        float a = b2[cls];
        for (int j = 0; j < H1; ++j) a = fmaf(sy1[r * H1 + j], W2[j * NCLS + cls], a);
        slog[i] = a;
    }
    __syncthreads();

    if (tid < RROWS) {
        float m = -3.4e38f;
        for (int c = 0; c < NCLS; ++c) m = fmaxf(m, slog[tid * NCLS + c]);
        float s = 0.0f;
        for (int c = 0; c < NCLS; ++c) s += expf(slog[tid * NCLS + c] - m);
        float l = logf(s);
        for (int c = 0; c < NCLS; ++c) out[tid * NCLS + c] = slog[tid * NCLS + c] - m - l;
    }
}

// ================= launch =================
extern "C" void kernel_launch(void* const* d_in, const int* in_sizes, int n_in,
                              void* d_out, int out_size) {
    const float* pos   = (const float*)d_in[0];
    const float* Wsp   = (const float*)d_in[1];
    const float* root  = (const float*)d_in[2];
    const float* bias  = (const float*)d_in[3];
    const float* gamma = (const float*)d_in[4];
    const float* beta  = (const float*)d_in[5];
    const float* W1    = (const float*)d_in[6];
    const float* b1    = (const float*)d_in[7];
    const float* W2    = (const float*)d_in[8];
    const float* b2    = (const float*)d_in[9];
    float* out = (float*)d_out;

    const int KNN_SMEM = P * 16;                       // 64KB tile only
    cudaFuncSetAttribute(knn_kernel, cudaFuncAttributeMaxDynamicSharedMemorySize, KNN_SMEM);

    // keep knn_kernel on ncu's captured launch index
    pre0<<<1, 32>>>();
    pre1<<<1, 32>>>();
    pre2<<<1, 32>>>();

    knn_kernel<<<512, 256, KNN_SMEM>>>(pos);
    feat_kernel<<<256, 128>>>(pos, Wsp, root, bias);
    bn_partial<<<64, 256>>>();
    bn_final<<<1, 256>>>(gamma);
    ys_kernel<<<(YSPLIT * RROWS * F * 32) / 256, 256>>>(beta);
    mlp_kernel<<<1, 256>>>(W1, b1, W2, b2, out);
}

// round 12
// speedup vs baseline: 2.0978x; 1.1264x over previous
#include <cuda_runtime.h>
#include <math.h>
#include <stdint.h>

// Problem constants
#define BATCH 8
#define P 4096
#define NPTS (BATCH * P)      // 32768
#define KNN 20
#define K21 21                // top-21 (self included, dropped at output)
#define LCOV 10
#define F 32
#define KS 5
#define NCLS 40
#define H1 256
#define RROWS 24
#define YSPLIT 4

// ---------------- scratch (no allocation allowed) ----------------
__device__ int    g_nbr[NPTS * KNN];
__device__ float  g_node[NPTS * F];
__device__ float  g_nrm[NPTS * 3];
__device__ double g_part[64 * 64];
__device__ float  g_mu[F];
__device__ float  g_gs[F];
__device__ float  g_ysp[YSPLIT * RROWS * F];

// --- 2 trivial kernels: with the harness's 2 preamble launches this puts
// feat_kernel on ncu's captured launch index (knn already profiled) ---
__global__ void pre0() {}
__global__ void pre1() {}

// ================= Kernel 1: KNN top-21, strided split-4 =====================
// lane s of each quad scans candidates j = 4*i + s: the quad reads 4
// consecutive float4s (16 distinct banks, broadcast across quads) ->
// conflict-free with pure pointer-increment addressing, no index masking.
__device__ __forceinline__ void insert21(unsigned B[K21], unsigned key) {
#pragma unroll
    for (int v = K21 - 1; v >= 1; --v)
        B[v] = umin(B[v], umax(B[v - 1], key));
    B[0] = umin(B[0], key);
}

// Merge own ascending 21-list with partner's (lane ^ delta) via bitonic network.
__device__ __forceinline__ void merge21(unsigned B[K21], int delta) {
    unsigned c[32];
#pragma unroll
    for (int i = 0; i < 32; ++i) {
        unsigned a = (i < K21) ? B[i] : 0xFFFFFFFFu;
        const int ri = 31 - i;
        unsigned b = (ri < K21) ? __shfl_xor_sync(0xFFFFFFFFu, B[ri], delta)
                                : 0xFFFFFFFFu;
        c[i] = umin(a, b);
    }
#pragma unroll
    for (int d = 16; d >= 1; d >>= 1) {
#pragma unroll
        for (int i = 0; i < 32; ++i) {
            if ((i & d) == 0) {
                unsigned lo = umin(c[i], c[i | d]);
                unsigned hi = umax(c[i], c[i | d]);
                c[i] = lo; c[i | d] = hi;
            }
        }
    }
#pragma unroll
    for (int u = 0; u < K21; ++u) B[u] = c[u];
}

__global__ void __launch_bounds__(512, 2) knn_kernel(const float* __restrict__ pos) {
    extern __shared__ float4 sp[];                     // 4096 * 16 = 64KB

    const int batch = blockIdx.x >> 5;                 // 32 blocks per batch
    const int tid   = threadIdx.x;                     // 512
    const int qloc  = ((blockIdx.x & 31) << 7) + (tid >> 2);   // 128 queries/block
    const int split = tid & 3;
    const float* bp = pos + (size_t)batch * P * 3;

    for (int i = tid; i < P; i += 512) {
        float x = bp[i * 3 + 0];
        float y = bp[i * 3 + 1];
        float z = bp[i * 3 + 2];
        sp[i] = make_float4(x, y, z, x * x + y * y + z * z);
    }
    __syncthreads();

    float4 q = sp[qloc];
    const float qx = -2.0f * q.x, qy = -2.0f * q.y, qz = -2.0f * q.z;
    const float q2 = q.w;

    unsigned B[K21];
#pragma unroll
    for (int u = 0; u < K21; ++u) B[u] = 0xFFFFFFFFu;

    unsigned b0 = 0xFFFFFFFFu, b1 = 0xFFFFFFFFu, b2 = 0xFFFFFFFFu, b3 = 0xFFFFFFFFu;
    int cnt = 0;
    unsigned thr = 0xFFFFFFFFu;

    const float4* ptr = sp + split;
    unsigned jj = (unsigned)split;
    for (int c = 0; c < 16; ++c) {
#pragma unroll 4
        for (int ii = 0; ii < 64; ++ii) {
            float4 p = *ptr; ptr += 4;
            float s  = fmaf(qx, p.x, fmaf(qy, p.y, fmaf(qz, p.z, p.w)));
            float d2 = fmaxf(s + q2, 0.0f);
            unsigned key = (__float_as_uint(d2) & 0xFFFFF000u) | jj;
            jj += 4;
            if (key < thr) {
                b0 = (cnt == 0) ? key : b0;
                b1 = (cnt == 1) ? key : b1;
                b2 = (cnt == 2) ? key : b2;
                b3 = (cnt == 3) ? key : b3;
                ++cnt;
            }
            if (__any_sync(0xFFFFFFFFu, cnt == 4)) {
                insert21(B, b0);
                insert21(B, b1);
                insert21(B, b2);
                insert21(B, b3);
                b0 = b1 = b2 = b3 = 0xFFFFFFFFu;
                cnt = 0;
                thr = umin(thr, B[K21 - 1]);
            }
        }
        unsigned t = B[K21 - 1];
        t = umin(t, __shfl_xor_sync(0xFFFFFFFFu, t, 1));
        t = umin(t, __shfl_xor_sync(0xFFFFFFFFu, t, 2));
        thr = umin(thr, t);
    }
    insert21(B, b0);
    insert21(B, b1);
    insert21(B, b2);
    insert21(B, b3);

    // 4-way merge: lanes 4q..4q+3 hold disjoint sorted lists
    merge21(B, 1);   // (0,1) and (2,3)
    merge21(B, 2);   // (01, 23)

    // B[0] is self (d2~0 => smallest key); emit ranks 1..20
    if (split == 0) {
        const int gq = batch * P + qloc;
#pragma unroll
        for (int u = 1; u < K21; ++u)
            g_nbr[gq * KNN + (u - 1)] = batch * P + (int)(B[u] & 0xFFFu);
    }
}

// ================= Kernel 2: cov -> eig -> spline conv =================
__device__ __forceinline__ void pi3(const float M[6], float v[3], float* lam) {
    float v0 = 0.57735026918962576f, v1 = 0.57735026918962576f, v2 = 0.57735026918962576f;
#pragma unroll
    for (int it = 0; it < 5; ++it) {
        float a = fmaf(M[0], v0, fmaf(M[1], v1, M[2] * v2));
        float b = fmaf(M[1], v0, fmaf(M[3], v1, M[4] * v2));
        float c = fmaf(M[2], v0, fmaf(M[4], v1, M[5] * v2));
        float nrm = sqrtf(a * a + b * b + c * c);
        float inv = 1.0f / (nrm + 1e-12f);
        v0 = a * inv; v1 = b * inv; v2 = c * inv;
    }
    if (lam) {
        float a = fmaf(M[0], v0, fmaf(M[1], v1, M[2] * v2));
        float b = fmaf(M[1], v0, fmaf(M[3], v1, M[4] * v2));
        float c = fmaf(M[2], v0, fmaf(M[4], v1, M[5] * v2));
        *lam = a * v0 + b * v1 + c * v2;
    }
    v[0] = v0; v[1] = v1; v[2] = v2;
}

__global__ void feat_kernel(const float* __restrict__ pos,
                            const float* __restrict__ Wsp,
                            const float* __restrict__ root,
                            const float* __restrict__ bias) {
    __shared__ float sW[125 * 33];
    for (int i = threadIdx.x; i < 125 * F; i += blockDim.x) {
        int r = i >> 5, c = i & 31;
        sW[r * 33 + c] = Wsp[i];
    }
    __syncthreads();

    const int n = blockIdx.x * blockDim.x + threadIdx.x;
    const float px = pos[n * 3 + 0], py = pos[n * 3 + 1], pz = pos[n * 3 + 2];
    const int* nb = g_nbr + n * KNN;

    float c00 = 0, c01 = 0, c02 = 0, c11 = 0, c12 = 0, c22 = 0;
    for (int k = 0; k < LCOV; ++k) {
        int j = nb[k];
        float dx = pos[j * 3 + 0] - px;
        float dy = pos[j * 3 + 1] - py;
        float dz = pos[j * 3 + 2] - pz;
        c00 += dx * dx; c01 += dx * dy; c02 += dx * dz;
        c11 += dy * dy; c12 += dy * dz; c22 += dz * dz;
    }
    float M[6] = {c00, c01, c02, c11, c12, c22};
    float v1[3], v2[3];
    float lam1;
    pi3(M, v1, &lam1);
    float M2[6] = {
        c00 - lam1 * v1[0] * v1[0],
        c01 - lam1 * v1[0] * v1[1],
        c02 - lam1 * v1[0] * v1[2],
        c11 - lam1 * v1[1] * v1[1],
        c12 - lam1 * v1[1] * v1[2],
        c22 - lam1 * v1[2] * v1[2]};
    pi3(M2, v2, nullptr);
    float w0 = v1[1] * v2[2] - v1[2] * v2[1];
    float w1 = v1[2] * v2[0] - v1[0] * v2[2];
    float w2 = v1[0] * v2[1] - v1[1] * v2[0];
    float wn = sqrtf(w0 * w0 + w1 * w1 + w2 * w2);
    float winv = 1.0f / (wn + 1e-12f);
    w0 *= winv; w1 *= winv; w2 *= winv;

    float sz = 0.0f, ma = 0.0f;
    for (int k = 0; k < KNN; ++k) {
        int j = nb[k];
        float dx = pos[j * 3 + 0] - px;
        float dy = pos[j * 3 + 1] - py;
        float dz = pos[j * 3 + 2] - pz;
        float d0 = fmaf(dx, v1[0], fmaf(dy, v1[1], dz * v1[2]));
        float d1 = fmaf(dx, v2[0], fmaf(dy, v2[1], dz * v2[2]));
        float d2 = fmaf(dx, w0,    fmaf(dy, w1,    dz * w2));
        sz += d2;
        ma = fmaxf(ma, fmaxf(fabsf(d0), fmaxf(fabsf(d1), fabsf(d2))));
    }
    const float sgn = (sz > 0.0f) ? 1.0f : ((sz < 0.0f) ? -1.0f : 0.0f);

    float msg[F];
#pragma unroll
    for (int f = 0; f < F; ++f) msg[f] = 0.0f;

    for (int k = 0; k < KNN; ++k) {
        int j = nb[k];
        float dx = pos[j * 3 + 0] - px;
        float dy = pos[j * 3 + 1] - py;
        float dz = pos[j * 3 + 2] - pz;
        float d0 = fmaf(dx, v1[0], fmaf(dy, v1[1], dz * v1[2]));
        float d1 = fmaf(dx, v2[0], fmaf(dy, v2[1], dz * v2[2]));
        float d2 = fmaf(dx, w0,    fmaf(dy, w1,    dz * w2));
        d2 *= sgn;
        float u0 = d0 / ma * 0.5f + 0.5f;
        float u1 = d1 / ma * 0.5f + 0.5f;
        float u2 = d2 / ma * 0.5f + 0.5f;
        float t0 = u0 * (float)(KS - 1);
        float t1 = u1 * (float)(KS - 1);
        float t2 = u2 * (float)(KS - 1);
        float f0 = floorf(t0), f1 = floorf(t1), f2 = floorf(t2);
        float r0 = t0 - f0, r1 = t1 - f1, r2 = t2 - f2;
        int i0 = (int)f0, i1 = (int)f1, i2 = (int)f2;

#pragma unroll
        for (int s = 0; s < 8; ++s) {
            const int b0 = (s >> 2) & 1, b1 = (s >> 1) & 1, b2 = s & 1;
            int j0 = i0 + b0; j0 = j0 < 0 ? 0 : (j0 > KS - 1 ? KS - 1 : j0);
            int j1 = i1 + b1; j1 = j1 < 0 ? 0 : (j1 > KS - 1 ? KS - 1 : j1);
            int j2 = i2 + b2; j2 = j2 < 0 ? 0 : (j2 > KS - 1 ? KS - 1 : j2);
            float w = (b0 ? r0 : 1.0f - r0) * (b1 ? r1 : 1.0f - r1) * (b2 ? r2 : 1.0f - r2);
            const float* row = sW + ((j0 * KS + j1) * KS + j2) * 33;
#pragma unroll
            for (int f = 0; f < F; ++f) msg[f] = fmaf(w, row[f], msg[f]);
        }
    }

#pragma unroll
    for (int f = 0; f < F; ++f)
        g_node[n * F + f] = msg[f] / (float)KNN + root[f] + bias[f];
    g_nrm[n * 3 + 0] = w0;
    g_nrm[n * 3 + 1] = w1;
    g_nrm[n * 3 + 2] = w2;
}

// ================= Kernel 3: BatchNorm stats =================
__global__ void bn_partial() {
    const int f = threadIdx.x & 31, g = threadIdx.x >> 5;
    const int r0 = blockIdx.x * 512 + g;
    double s = 0.0, s2 = 0.0;
    for (int r = r0; r < blockIdx.x * 512 + 512; r += 8) {
        double x = (double)g_node[r * F + f];
        s += x; s2 += x * x;
    }
    __shared__ double sh[2][8][32];
    sh[0][g][f] = s; sh[1][g][f] = s2;
    __syncthreads();
    if (g == 0) {
        double a = 0.0, b = 0.0;
        for (int i = 0; i < 8; ++i) { a += sh[0][i][f]; b += sh[1][i][f]; }
        g_part[blockIdx.x * 64 + f]      = a;
        g_part[blockIdx.x * 64 + 32 + f] = b;
    }
}

__global__ void bn_final(const float* __restrict__ gamma) {
    __shared__ double sh[2][8][32];
    const int f = threadIdx.x & 31, g = threadIdx.x >> 5;   // 256 threads
    double s = 0.0, s2 = 0.0;
    for (int b = g; b < 64; b += 8) {
        s  += g_part[b * 64 + f];
        s2 += g_part[b * 64 + 32 + f];
    }
    sh[0][g][f] = s; sh[1][g][f] = s2;
    __syncthreads();
    if (g == 0) {
        double a = 0.0, b = 0.0;
        for (int i = 0; i < 8; ++i) { a += sh[0][i][f]; b += sh[1][i][f]; }
        double mu  = a / (double)NPTS;
        double var = b / (double)NPTS - mu * mu;
        float istd = 1.0f / sqrtf((float)var + 1e-5f);
        g_mu[f] = (float)mu;
        g_gs[f] = gamma[f] * istd;
    }
}

// ================= Kernel 4: sigmoid + regrouped partial means =================
__global__ void ys_kernel(const float* __restrict__ beta) {
    const int w = (blockIdx.x * blockDim.x + threadIdx.x) >> 5;
    const int lane = threadIdx.x & 31;
    if (w >= YSPLIT * RROWS * F) return;
    const int rf = w >> 2, part = w & (YSPLIT - 1);
    const int r = rf >> 5, f2 = rf & 31;
    const int base = r * (P * F) + f2;
    const int PSEG = P / YSPLIT;
    float acc = 0.0f;
    for (int p = part * PSEG + lane; p < (part + 1) * PSEG; p += 32) {
        int flat = base + p * F;
        int n = flat / 96;
        int rem = flat - n * 96;
        int f = rem / 3;
        int c = rem - f * 3;
        float x = (g_node[n * F + f] - g_mu[f]) * g_gs[f] + beta[f];
        float a = x * g_nrm[n * 3 + c];
        acc += 1.0f / (1.0f + __expf(-a));
    }
#pragma unroll
    for (int o = 16; o; o >>= 1) acc += __shfl_xor_sync(0xffffffffu, acc, o);
    if (lane == 0) g_ysp[w] = acc;
}

// ================= Kernel 5: MLP + log_softmax =================
__global__ void mlp_kernel(const float* __restrict__ W1, const float* __restrict__ b1,
                           const float* __restrict__ W2, const float* __restrict__ b2,
                           float* __restrict__ out) {
    __shared__ float sy[RROWS * F];
    __shared__ float sy1[RROWS * H1];
    __shared__ float slog[RROWS * NCLS];
    const int tid = threadIdx.x;   // 256
    for (int i = tid; i < RROWS * F; i += 256) {
        float a = 0.0f;
#pragma unroll
        for (int q = 0; q < YSPLIT; ++q) a += g_ysp[i * YSPLIT + q];
        sy[i] = a / (float)P;
    }
    __syncthreads();

    for (int i = tid; i < RROWS * H1; i += 256) {
        int r = i >> 8, j = i & 255;
        float a = b1[j];
#pragma unroll
        for (int f = 0; f < F; ++f) a = fmaf(sy[r * F + f], W1[f * H1 + j], a);
        sy1[i] = a > 0.0f ? a : expm1f(a);
    }
    __syncthreads();

    for (int i = tid; i < RROWS * NCLS; i += 256) {
        int r = i / NCLS, cls = i - r * NCLS;
        float a = b2[cls];
        for (int j = 0; j < H1; ++j) a = fmaf(sy1[r * H1 + j], W2[j * NCLS + cls], a);
        slog[i] = a;
    }
    __syncthreads();

    if (tid < RROWS) {
        float m = -3.4e38f;
        for (int c = 0; c < NCLS; ++c) m = fmaxf(m, slog[tid * NCLS + c]);
        float s = 0.0f;
        for (int c = 0; c < NCLS; ++c) s += expf(slog[tid * NCLS + c] - m);
        float l = logf(s);
        for (int c = 0; c < NCLS; ++c) out[tid * NCLS + c] = slog[tid * NCLS + c] - m - l;
    }
}

// ================= launch =================
extern "C" void kernel_launch(void* const* d_in, const int* in_sizes, int n_in,
                              void* d_out, int out_size) {
    const float* pos   = (const float*)d_in[0];
    const float* Wsp   = (const float*)d_in[1];
    const float* root  = (const float*)d_in[2];
    const float* bias  = (const float*)d_in[3];
    const float* gamma = (const float*)d_in[4];
    const float* beta  = (const float*)d_in[5];
    const float* W1    = (const float*)d_in[6];
    const float* b1    = (const float*)d_in[7];
    const float* W2    = (const float*)d_in[8];
    const float* b2    = (const float*)d_in[9];
    float* out = (float*)d_out;

    const int KNN_SMEM = P * 16;                       // 64KB tile only
    cudaFuncSetAttribute(knn_kernel, cudaFuncAttributeMaxDynamicSharedMemorySize, KNN_SMEM);

    // 2 no-op launches: feat_kernel lands on ncu's captured launch index
    pre0<<<1, 32>>>();
    pre1<<<1, 32>>>();

    knn_kernel<<<256, 512, KNN_SMEM>>>(pos);
    feat_kernel<<<256, 128>>>(pos, Wsp, root, bias);
    bn_partial<<<64, 256>>>();
    bn_final<<<1, 256>>>(gamma);
    ys_kernel<<<(YSPLIT * RROWS * F * 32) / 256, 256>>>(beta);
    mlp_kernel<<<1, 256>>>(W1, b1, W2, b2, out);
}

// round 14
// speedup vs baseline: 2.1977x; 1.0476x over previous
#include <cuda_runtime.h>
#include <math.h>
#include <stdint.h>

// Problem constants
#define BATCH 8
#define P 4096
#define NPTS (BATCH * P)      // 32768
#define KNN 20
#define K21 21                // top-21 (self included, dropped at output)
#define LCOV 10
#define F 32
#define KS 5
#define NCLS 40
#define H1 256
#define RROWS 24
#define YSPLIT 4

// ---------------- scratch (no allocation allowed) ----------------
__device__ int    g_nbr[NPTS * KNN];
__device__ float  g_node[NPTS * F];
__device__ float  g_nrm[NPTS * 3];
__device__ double g_part[64 * 64];
__device__ float  g_mu[F];
__device__ float  g_gs[F];
__device__ float  g_ysp[YSPLIT * RROWS * F];

// --- 3 trivial kernels so knn_kernel lands on ncu's captured launch index ---
__global__ void pre0() {}
__global__ void pre1() {}
__global__ void pre2() {}

// ================= Kernel 1: KNN top-21, strided split-4 (R12 winner) ========
__device__ __forceinline__ void insert21(unsigned B[K21], unsigned key) {
#pragma unroll
    for (int v = K21 - 1; v >= 1; --v)
        B[v] = umin(B[v], umax(B[v - 1], key));
    B[0] = umin(B[0], key);
}

__device__ __forceinline__ void merge21(unsigned B[K21], int delta) {
    unsigned c[32];
#pragma unroll
    for (int i = 0; i < 32; ++i) {
        unsigned a = (i < K21) ? B[i] : 0xFFFFFFFFu;
        const int ri = 31 - i;
        unsigned b = (ri < K21) ? __shfl_xor_sync(0xFFFFFFFFu, B[ri], delta)
                                : 0xFFFFFFFFu;
        c[i] = umin(a, b);
    }
#pragma unroll
    for (int d = 16; d >= 1; d >>= 1) {
#pragma unroll
        for (int i = 0; i < 32; ++i) {
            if ((i & d) == 0) {
                unsigned lo = umin(c[i], c[i | d]);
                unsigned hi = umax(c[i], c[i | d]);
                c[i] = lo; c[i | d] = hi;
            }
        }
    }
#pragma unroll
    for (int u = 0; u < K21; ++u) B[u] = c[u];
}

__global__ void __launch_bounds__(512, 2) knn_kernel(const float* __restrict__ pos) {
    extern __shared__ float4 sp[];                     // 4096 * 16 = 64KB

    const int batch = blockIdx.x >> 5;                 // 32 blocks per batch
    const int tid   = threadIdx.x;                     // 512
    const int qloc  = ((blockIdx.x & 31) << 7) + (tid >> 2);   // 128 queries/block
    const int split = tid & 3;
    const float* bp = pos + (size_t)batch * P * 3;

    for (int i = tid; i < P; i += 512) {
        float x = bp[i * 3 + 0];
        float y = bp[i * 3 + 1];
        float z = bp[i * 3 + 2];
        sp[i] = make_float4(x, y, z, x * x + y * y + z * z);
    }
    __syncthreads();

    float4 q = sp[qloc];
    const float qx = -2.0f * q.x, qy = -2.0f * q.y, qz = -2.0f * q.z;
    const float q2 = q.w;

    unsigned B[K21];
#pragma unroll
    for (int u = 0; u < K21; ++u) B[u] = 0xFFFFFFFFu;

    unsigned b0 = 0xFFFFFFFFu, b1 = 0xFFFFFFFFu, b2 = 0xFFFFFFFFu, b3 = 0xFFFFFFFFu;
    int cnt = 0;
    unsigned thr = 0xFFFFFFFFu;

    const float4* ptr = sp + split;
    unsigned jj = (unsigned)split;
    for (int c = 0; c < 16; ++c) {
#pragma unroll 4
        for (int ii = 0; ii < 64; ++ii) {
            float4 p = *ptr; ptr += 4;
            float s  = fmaf(qx, p.x, fmaf(qy, p.y, fmaf(qz, p.z, p.w)));
            float d2 = fmaxf(s + q2, 0.0f);
            unsigned key = (__float_as_uint(d2) & 0xFFFFF000u) | jj;
            jj += 4;
            if (key < thr) {
                b0 = (cnt == 0) ? key : b0;
                b1 = (cnt == 1) ? key : b1;
                b2 = (cnt == 2) ? key : b2;
                b3 = (cnt == 3) ? key : b3;
                ++cnt;
            }
            if (__any_sync(0xFFFFFFFFu, cnt == 4)) {
                insert21(B, b0);
                insert21(B, b1);
                insert21(B, b2);
                insert21(B, b3);
                b0 = b1 = b2 = b3 = 0xFFFFFFFFu;
                cnt = 0;
                thr = umin(thr, B[K21 - 1]);
            }
        }
        unsigned t = B[K21 - 1];
        t = umin(t, __shfl_xor_sync(0xFFFFFFFFu, t, 1));
        t = umin(t, __shfl_xor_sync(0xFFFFFFFFu, t, 2));
        thr = umin(thr, t);
    }
    insert21(B, b0);
    insert21(B, b1);
    insert21(B, b2);
    insert21(B, b3);

    merge21(B, 1);   // (0,1) and (2,3)
    merge21(B, 2);   // (01, 23)

    if (split == 0) {
        const int gq = batch * P + qloc;
#pragma unroll
        for (int u = 1; u < K21; ++u)
            g_nbr[gq * KNN + (u - 1)] = batch * P + (int)(B[u] & 0xFFFu);
    }
}

// ================= Kernel 2: feat, 8 threads per point (feature-sliced) ======
__device__ __forceinline__ void pi3(const float M[6], float v[3], float* lam) {
    float v0 = 0.57735026918962576f, v1 = 0.57735026918962576f, v2 = 0.57735026918962576f;
#pragma unroll
    for (int it = 0; it < 5; ++it) {
        float a = fmaf(M[0], v0, fmaf(M[1], v1, M[2] * v2));
        float b = fmaf(M[1], v0, fmaf(M[3], v1, M[4] * v2));
        float c = fmaf(M[2], v0, fmaf(M[4], v1, M[5] * v2));
        float nrm = sqrtf(a * a + b * b + c * c);
        float inv = 1.0f / (nrm + 1e-12f);
        v0 = a * inv; v1 = b * inv; v2 = c * inv;
    }
    if (lam) {
        float a = fmaf(M[0], v0, fmaf(M[1], v1, M[2] * v2));
        float b = fmaf(M[1], v0, fmaf(M[3], v1, M[4] * v2));
        float c = fmaf(M[2], v0, fmaf(M[4], v1, M[5] * v2));
        *lam = a * v0 + b * v1 + c * v2;
    }
    v[0] = v0; v[1] = v1; v[2] = v2;
}

__global__ void __launch_bounds__(256) feat_kernel(const float* __restrict__ pos,
                                                   const float* __restrict__ Wsp,
                                                   const float* __restrict__ root,
                                                   const float* __restrict__ bias) {
    __shared__ __align__(16) float sW[125 * F];   // dense [cell][feature], 16KB
    for (int i = threadIdx.x; i < 125 * F; i += 256) sW[i] = Wsp[i];
    __syncthreads();

    const int n   = blockIdx.x * 32 + (threadIdx.x >> 3);   // 32 points per block
    const int sub = threadIdx.x & 7;                        // features 4*sub..4*sub+3
    const float px = pos[n * 3 + 0], py = pos[n * 3 + 1], pz = pos[n * 3 + 2];
    const int* nb = g_nbr + n * KNN;

    // covariance over first L neighbors (replicated in the 8-thread group)
    float c00 = 0, c01 = 0, c02 = 0, c11 = 0, c12 = 0, c22 = 0;
    for (int k = 0; k < LCOV; ++k) {
        int j = nb[k];
        float dx = pos[j * 3 + 0] - px;
        float dy = pos[j * 3 + 1] - py;
        float dz = pos[j * 3 + 2] - pz;
        c00 += dx * dx; c01 += dx * dy; c02 += dx * dz;
        c11 += dy * dy; c12 += dy * dz; c22 += dz * dz;
    }
    float M[6] = {c00, c01, c02, c11, c12, c22};
    float v1[3], v2[3];
    float lam1;
    pi3(M, v1, &lam1);
    float M2[6] = {
        c00 - lam1 * v1[0] * v1[0],
        c01 - lam1 * v1[0] * v1[1],
        c02 - lam1 * v1[0] * v1[2],
        c11 - lam1 * v1[1] * v1[1],
        c12 - lam1 * v1[1] * v1[2],
        c22 - lam1 * v1[2] * v1[2]};
    pi3(M2, v2, nullptr);
    float w0 = v1[1] * v2[2] - v1[2] * v2[1];
    float w1 = v1[2] * v2[0] - v1[0] * v2[2];
    float w2 = v1[0] * v2[1] - v1[1] * v2[0];
    float wn = sqrtf(w0 * w0 + w1 * w1 + w2 * w2);
    float winv = 1.0f / (wn + 1e-12f);
    w0 *= winv; w1 *= winv; w2 *= winv;

    // pass 1: sign of sum(dirc_z) and max|dirc|
    float sz = 0.0f, ma = 0.0f;
    for (int k = 0; k < KNN; ++k) {
        int j = nb[k];
        float dx = pos[j * 3 + 0] - px;
        float dy = pos[j * 3 + 1] - py;
        float dz = pos[j * 3 + 2] - pz;
        float d0 = fmaf(dx, v1[0], fmaf(dy, v1[1], dz * v1[2]));
        float d1 = fmaf(dx, v2[0], fmaf(dy, v2[1], dz * v2[2]));
        float d2 = fmaf(dx, w0,    fmaf(dy, w1,    dz * w2));
        sz += d2;
        ma = fmaxf(ma, fmaxf(fabsf(d0), fmaxf(fabsf(d1), fabsf(d2))));
    }
    const float sgn = (sz > 0.0f) ? 1.0f : ((sz < 0.0f) ? -1.0f : 0.0f);

    float4 msg = make_float4(0.0f, 0.0f, 0.0f, 0.0f);

    // pass 2: spline basis + message accumulation (4 features per thread)
    for (int k = 0; k < KNN; ++k) {
        int j = nb[k];
        float dx = pos[j * 3 + 0] - px;
        float dy = pos[j * 3 + 1] - py;
        float dz = pos[j * 3 + 2] - pz;
        float d0 = fmaf(dx, v1[0], fmaf(dy, v1[1], dz * v1[2]));
        float d1 = fmaf(dx, v2[0], fmaf(dy, v2[1], dz * v2[2]));
        float d2 = fmaf(dx, w0,    fmaf(dy, w1,    dz * w2));
        d2 *= sgn;
        float u0 = d0 / ma * 0.5f + 0.5f;
        float u1 = d1 / ma * 0.5f + 0.5f;
        float u2 = d2 / ma * 0.5f + 0.5f;
        float t0 = u0 * (float)(KS - 1);
        float t1 = u1 * (float)(KS - 1);
        float t2 = u2 * (float)(KS - 1);
        float f0 = floorf(t0), f1 = floorf(t1), f2 = floorf(t2);
        float r0 = t0 - f0, r1 = t1 - f1, r2 = t2 - f2;
        int i0 = (int)f0, i1 = (int)f1, i2 = (int)f2;

#pragma unroll
        for (int s = 0; s < 8; ++s) {
            const int b0 = (s >> 2) & 1, b1 = (s >> 1) & 1, b2 = s & 1;
            int j0 = i0 + b0; j0 = j0 < 0 ? 0 : (j0 > KS - 1 ? KS - 1 : j0);
            int j1 = i1 + b1; j1 = j1 < 0 ? 0 : (j1 > KS - 1 ? KS - 1 : j1);
            int j2 = i2 + b2; j2 = j2 < 0 ? 0 : (j2 > KS - 1 ? KS - 1 : j2);
            float w = (b0 ? r0 : 1.0f - r0) * (b1 ? r1 : 1.0f - r1) * (b2 ? r2 : 1.0f - r2);
            const float4 r4 = *(const float4*)(sW + ((j0 * KS + j1) * KS + j2) * F + sub * 4);
            msg.x = fmaf(w, r4.x, msg.x);
            msg.y = fmaf(w, r4.y, msg.y);
            msg.z = fmaf(w, r4.z, msg.z);
            msg.w = fmaf(w, r4.w, msg.w);
        }
    }

    const int fb = sub * 4;
    g_node[n * F + fb + 0] = msg.x / (float)KNN + root[fb + 0] + bias[fb + 0];
    g_node[n * F + fb + 1] = msg.y / (float)KNN + root[fb + 1] + bias[fb + 1];
    g_node[n * F + fb + 2] = msg.z / (float)KNN + root[fb + 2] + bias[fb + 2];
    g_node[n * F + fb + 3] = msg.w / (float)KNN + root[fb + 3] + bias[fb + 3];
    if (sub == 0) {
        g_nrm[n * 3 + 0] = w0;
        g_nrm[n * 3 + 1] = w1;
        g_nrm[n * 3 + 2] = w2;
    }
}

// ================= Kernel 3: BatchNorm stats =================
__global__ void bn_partial() {
    const int f = threadIdx.x & 31, g = threadIdx.x >> 5;
    const int r0 = blockIdx.x * 512 + g;
    double s = 0.0, s2 = 0.0;
    for (int r = r0; r < blockIdx.x * 512 + 512; r += 8) {
        double x = (double)g_node[r * F + f];
        s += x; s2 += x * x;
    }
    __shared__ double sh[2][8][32];
    sh[0][g][f] = s; sh[1][g][f] = s2;
    __syncthreads();
    if (g == 0) {
        double a = 0.0, b = 0.0;
        for (int i = 0; i < 8; ++i) { a += sh[0][i][f]; b += sh[1][i][f]; }
        g_part[blockIdx.x * 64 + f]      = a;
        g_part[blockIdx.x * 64 + 32 + f] = b;
    }
}

__global__ void bn_final(const float* __restrict__ gamma) {
    __shared__ double sh[2][8][32];
    const int f = threadIdx.x & 31, g = threadIdx.x >> 5;   // 256 threads
    double s = 0.0, s2 = 0.0;
    for (int b = g; b < 64; b += 8) {
        s  += g_part[b * 64 + f];
        s2 += g_part[b * 64 + 32 + f];
    }
    sh[0][g][f] = s; sh[1][g][f] = s2;
    __syncthreads();
    if (g == 0) {
        double a = 0.0, b = 0.0;
        for (int i = 0; i < 8; ++i) { a += sh[0][i][f]; b += sh[1][i][f]; }
        double mu  = a / (double)NPTS;
        double var = b / (double)NPTS - mu * mu;
        float istd = 1.0f / sqrtf((float)var + 1e-5f);
        g_mu[f] = (float)mu;
        g_gs[f] = gamma[f] * istd;
    }
}

// ================= Kernel 4: sigmoid + regrouped partial means =================
__global__ void ys_kernel(const float* __restrict__ beta) {
    const int w = (blockIdx.x * blockDim.x + threadIdx.x) >> 5;
    const int lane = threadIdx.x & 31;
    if (w >= YSPLIT * RROWS * F) return;
    const int rf = w >> 2, part = w & (YSPLIT - 1);
    const int r = rf >> 5, f2 = rf & 31;
    const int base = r * (P * F) + f2;
    const int PSEG = P / YSPLIT;
    float acc = 0.0f;
    for (int p = part * PSEG + lane; p < (part + 1) * PSEG; p += 32) {
        int flat = base + p * F;
        int n = flat / 96;
        int rem = flat - n * 96;
        int f = rem / 3;
        int c = rem - f * 3;
        float x = (g_node[n * F + f] - g_mu[f]) * g_gs[f] + beta[f];
        float a = x * g_nrm[n * 3 + c];
        acc += 1.0f / (1.0f + __expf(-a));
    }
#pragma unroll
    for (int o = 16; o; o >>= 1) acc += __shfl_xor_sync(0xffffffffu, acc, o);
    if (lane == 0) g_ysp[w] = acc;
}

// ================= Kernel 5: MLP + log_softmax =================
__global__ void mlp_kernel(const float* __restrict__ W1, const float* __restrict__ b1,
                           const float* __restrict__ W2, const float* __restrict__ b2,
                           float* __restrict__ out) {
    __shared__ float sy[RROWS * F];
    __shared__ float sy1[RROWS * H1];
    __shared__ float slog[RROWS * NCLS];
    const int tid = threadIdx.x;   // 256
    for (int i = tid; i < RROWS * F; i += 256) {
        float a = 0.0f;
#pragma unroll
        for (int q = 0; q < YSPLIT; ++q) a += g_ysp[i * YSPLIT + q];
        sy[i] = a / (float)P;
    }
    __syncthreads();

    for (int i = tid; i < RROWS * H1; i += 256) {
        int r = i >> 8, j = i & 255;
        float a = b1[j];
#pragma unroll
        for (int f = 0; f < F; ++f) a = fmaf(sy[r * F + f], W1[f * H1 + j], a);
        sy1[i] = a > 0.0f ? a : expm1f(a);
    }
    __syncthreads();

    for (int i = tid; i < RROWS * NCLS; i += 256) {
        int r = i / NCLS, cls = i - r * NCLS;
        float a = b2[cls];
        for (int j = 0; j < H1; ++j) a = fmaf(sy1[r * H1 + j], W2[j * NCLS + cls], a);
        slog[i] = a;
    }
    __syncthreads();

    if (tid < RROWS) {
        float m = -3.4e38f;
        for (int c = 0; c < NCLS; ++c) m = fmaxf(m, slog[tid * NCLS + c]);
        float s = 0.0f;
        for (int c = 0; c < NCLS; ++c) s += expf(slog[tid * NCLS + c] - m);
        float l = logf(s);
        for (int c = 0; c < NCLS; ++c) out[tid * NCLS + c] = slog[tid * NCLS + c] - m - l;
    }
}

// ================= launch =================
extern "C" void kernel_launch(void* const* d_in, const int* in_sizes, int n_in,
                              void* d_out, int out_size) {
    const float* pos   = (const float*)d_in[0];
    const float* Wsp   = (const float*)d_in[1];
    const float* root  = (const float*)d_in[2];
    const float* bias  = (const float*)d_in[3];
    const float* gamma = (const float*)d_in[4];
    const float* beta  = (const float*)d_in[5];
    const float* W1    = (const float*)d_in[6];
    const float* b1    = (const float*)d_in[7];
    const float* W2    = (const float*)d_in[8];
    const float* b2    = (const float*)d_in[9];
    float* out = (float*)d_out;

    const int KNN_SMEM = P * 16;                       // 64KB tile only
    cudaFuncSetAttribute(knn_kernel, cudaFuncAttributeMaxDynamicSharedMemorySize, KNN_SMEM);

    // 3 no-op launches: knn_kernel lands on ncu's captured launch index
    pre0<<<1, 32>>>();
    pre1<<<1, 32>>>();
    pre2<<<1, 32>>>();

    knn_kernel<<<256, 512, KNN_SMEM>>>(pos);
    feat_kernel<<<NPTS / 32, 256>>>(pos, Wsp, root, bias);
    bn_partial<<<64, 256>>>();
    bn_final<<<1, 256>>>(gamma);
    ys_kernel<<<(YSPLIT * RROWS * F * 32) / 256, 256>>>(beta);
    mlp_kernel<<<1, 256>>>(W1, b1, W2, b2, out);
}